// round 7
// baseline (speedup 1.0000x reference)
#include <cuda_runtime.h>

#define TQ     900
#define TK     200
#define BATCH  128
#define LOG2E  1.4426950408889634f
#define LN2    0.6931471805599453f
#define EINV   0.36787944117144233f   // exp(-1): blank prob numerator
#define NTH    288                    // 1 DP warp + 8 producer warps
#define RINGR  48                     // ring depth in rows (6 chunks of 8)
#define ROWF   224                    // 7 probs per lane * 32 lanes

__device__ float g_losses[BATCH];
__device__ int   g_cnt = 0;

__device__ __forceinline__ float ex2f(float x) {
    float y; asm("ex2.approx.ftz.f32 %0, %1;" : "=f"(y) : "f"(x)); return y;
}
__device__ __forceinline__ float lg2f(float x) {
    float y; asm("lg2.approx.ftz.f32 %0, %1;" : "=f"(y) : "f"(x)); return y;
}
__device__ __forceinline__ float rcpf(float x) {
    float y; asm("rcp.approx.ftz.f32 %0, %1;" : "=f"(y) : "f"(x)); return y;
}

// One CTA per batch element (128 CTAs, ~1/SM). Warp 0 runs the whole CTC
// forward DP in linear (probability) domain: lane l owns pairs j=7l..7l+6 in
// registers; per step: 28 FADD/FMUL + 1 shfl_up + 7 conflict-free LDS.32 —
// no barriers, no MUFU on the serial chain. Underflow handled by exact pow2
// rescale every 4 steps (integer exponent accumulator C).
// Warps 1-8 produce softmax probs (pre-divided, label-masked) row-interleaved
// (t = pw mod 8) into a 48-row smem ring, with per-row generation flags and
// chunk-granular backpressure. Next-row logits are register-prefetched so the
// global-load latency is overlapped.
__global__ __launch_bounds__(NTH, 1)
void ctc_kernel(const float* __restrict__ attn,
                const int*   __restrict__ in_lens,
                const int*   __restrict__ out_lens,
                float*       __restrict__ out)
{
    __shared__ float s_p[RINGR][ROWF];
    __shared__ float s_pb[RINGR];
    __shared__ volatile int s_done[RINGR];   // row-generation flags (value = t)
    __shared__ volatile int s_cons;          // chunks consumed by DP warp
    __shared__ float s_fe[224], s_fo[224];

    const int b    = blockIdx.x;
    const int tid  = threadIdx.x;
    const int lane = tid & 31;
    const int w    = tid >> 5;
    const int L       = in_lens[b];    // 100..200
    const int out_len = out_lens[b];   // 700..900
    const float* attn_b = attn + (size_t)b * TQ * TK;
    const int nchunks = (out_len + 7) >> 3;

    // init: dead prob slots (>=200) must read 0 forever; flags to -1
    for (int i = tid; i < RINGR * ROWF; i += NTH) (&s_p[0][0])[i] = 0.f;
    for (int i = tid; i < RINGR; i += NTH) s_done[i] = -1;
    if (tid == 0) s_cons = 0;
    __syncthreads();

    if (w > 0) {
        // ---------------- Producer warps (8), rows t = pw (mod 8) --------
        const int pw = w - 1;
        int kk[7]; bool kv[7];
        #pragma unroll
        for (int i = 0; i < 7; ++i) { kk[i] = lane + 32 * i; kv[i] = (kk[i] < TK); }

        float x[7];
        if (pw < out_len) {                       // prefetch first row
            const float* row = attn_b + (size_t)pw * TK;
            #pragma unroll
            for (int i = 0; i < 7; ++i) x[i] = kv[i] ? __ldg(row + kk[i]) : 0.f;
        }
        for (int t = pw; t < out_len; t += 8) {
            const int c = t >> 3;
            while (s_cons < c - 5) __nanosleep(128);   // slot t%48 free?

            float cur[7];
            #pragma unroll
            for (int i = 0; i < 7; ++i) cur[i] = x[i];
            if (t + 8 < out_len) {                // prefetch next row early
                const float* row = attn_b + (size_t)(t + 8) * TK;
                #pragma unroll
                for (int i = 0; i < 7; ++i) x[i] = kv[i] ? __ldg(row + kk[i]) : 0.f;
            }

            float e[7];
            float sum = 0.f;
            #pragma unroll
            for (int i = 0; i < 7; ++i) {
                e[i] = kv[i] ? ex2f(cur[i] * LOG2E) : 0.f;
                sum += e[i];
            }
            #pragma unroll
            for (int off = 16; off; off >>= 1)
                sum += __shfl_xor_sync(0xffffffffu, sum, off);
            sum += EINV;                          // blank term, ONCE (post-reduce)
            float rd = rcpf(sum);
            rd = rd * (2.0f - sum * rd);          // one NR step: near-exact 1/sum

            const int rr = t % RINGR;
            #pragma unroll
            for (int i = 0; i < 7; ++i)
                if (kv[i]) s_p[rr][kk[i]] = (kk[i] < L) ? e[i] * rd : 0.f;
            if (lane == 0) s_pb[rr] = EINV * rd;
            __threadfence_block();
            if (lane == 0) s_done[rr] = t;
        }
    } else {
        // ---------------- DP warp ----------------------------------------
        float ae[7], ao[7];
        #pragma unroll
        for (int i = 0; i < 7; ++i) { ae[i] = 0.f; ao[i] = 0.f; }
        int C = 0;                                // stored = true * 2^C
        const int sbase = lane * 7;

        for (int c = 0; c < nchunks; ++c) {
            const int base = c * 8;
            const int nr = min(8, out_len - base);
            for (int i = 0; i < nr; ++i)          // wait for this chunk's rows
                while (s_done[(base + i) % RINGR] != base + i) __nanosleep(64);
            __threadfence_block();

            for (int r = 0; r < nr; ++r) {
                const int t  = base + r;
                const int rr = t % RINGR;
                const float pb = s_pb[rr];
                float p[7];
                #pragma unroll
                for (int i = 0; i < 7; ++i) p[i] = s_p[rr][sbase + i];

                if (t == 0) {
                    if (lane == 0) { ae[0] = pb; ao[0] = p[0]; }
                    continue;
                }

                float a1in = __shfl_up_sync(0xffffffffu, ao[6], 1);
                if (lane == 0) a1in = 0.f;

                float tv[7];
                tv[0] = ae[0] + a1in;
                #pragma unroll
                for (int i = 1; i < 7; ++i) tv[i] = ae[i] + ao[i - 1];
                #pragma unroll
                for (int i = 0; i < 7; ++i) {
                    ao[i] = (ao[i] + tv[i]) * p[i];
                    ae[i] = tv[i] * pb;
                }

                if ((t & 3) == 3) {               // pow2 rescale to ~2^75
                    float m = 0.f;
                    #pragma unroll
                    for (int i = 0; i < 7; ++i) m = fmaxf(m, fmaxf(ae[i], ao[i]));
                    #pragma unroll
                    for (int off = 16; off; off >>= 1)
                        m = fmaxf(m, __shfl_xor_sync(0xffffffffu, m, off));
                    if (m > 0.f) {
                        int eb = (__float_as_int(m) >> 23) & 255;
                        int sh = 202 - eb;
                        sh = max(-120, min(120, sh));
                        const float sc = __int_as_float((sh + 127) << 23);
                        C += sh;
                        #pragma unroll
                        for (int i = 0; i < 7; ++i) { ae[i] *= sc; ao[i] *= sc; }
                    }
                }
            }
            __threadfence_block();
            if (lane == 0) s_cons = c + 1;
        }

        // fin = alpha at t=out_len-1; hi=fin[2L] (even of pair L),
        // lo=fin[2L-1] (odd of pair L-1)
        #pragma unroll
        for (int i = 0; i < 7; ++i) {
            s_fe[lane * 7 + i] = ae[i];
            s_fo[lane * 7 + i] = ao[i];
        }
        __syncwarp();
        if (lane == 0) {
            const float hi  = s_fe[L];
            const float lo  = s_fo[L - 1];
            float loss = -(lg2f(hi + lo) - (float)C) * LN2;
            if (!(loss < 1e20f)) loss = 0.0f;     // inf/NaN/huge -> 0
            g_losses[b] = loss / (float)L;
            __threadfence();
            const int n = atomicAdd(&g_cnt, 1);
            if (n == BATCH - 1) {                 // last CTA: deterministic mean
                __threadfence();
                float s = 0.f;
                for (int i = 0; i < BATCH; ++i) s += g_losses[i];
                out[0] = s * (1.0f / BATCH);
                g_cnt = 0;                        // reset for graph replay
                __threadfence();
            }
        }
    }
}

extern "C" void kernel_launch(void* const* d_in, const int* in_sizes, int n_in,
                              void* d_out, int out_size)
{
    const float* attn     = (const float*)d_in[0];
    const int*   in_lens  = (const int*)d_in[1];
    const int*   out_lens = (const int*)d_in[2];
    (void)in_sizes; (void)n_in; (void)out_size;

    ctc_kernel<<<BATCH, NTH>>>(attn, in_lens, out_lens, (float*)d_out);
}

// round 8
// speedup vs baseline: 1.7867x; 1.7867x over previous
#include <cuda_runtime.h>

#define TQ     900
#define TK     200
#define BATCH  128
#define LOG2E  1.4426950408889634f
#define LN2    0.6931471805599453f
#define EINV   0.36787944117144233f   // exp(-1): blank prob numerator
#define NTH    288                    // 1 DP warp + 8 producer warps
#define CR     6                      // rows per chunk
#define NSLOT  8                      // ring slots (one per producer warp)
#define ROWF   224                    // 7 probs per lane * 32 lanes

__device__ float g_losses[BATCH];
__device__ int   g_cnt = 0;

__device__ __forceinline__ float ex2f(float x) {
    float y; asm("ex2.approx.ftz.f32 %0, %1;" : "=f"(y) : "f"(x)); return y;
}
__device__ __forceinline__ float lg2f(float x) {
    float y; asm("lg2.approx.ftz.f32 %0, %1;" : "=f"(y) : "f"(x)); return y;
}
__device__ __forceinline__ float rcpf(float x) {
    float y; asm("rcp.approx.ftz.f32 %0, %1;" : "=f"(y) : "f"(x)); return y;
}
__device__ __forceinline__ void mbar_init(unsigned a, unsigned cnt) {
    asm volatile("mbarrier.init.shared.b64 [%0], %1;" :: "r"(a), "r"(cnt) : "memory");
}
__device__ __forceinline__ void mbar_arrive(unsigned a) {
    asm volatile("mbarrier.arrive.release.cta.shared::cta.b64 _, [%0];" :: "r"(a) : "memory");
}
__device__ __forceinline__ void mbar_wait(unsigned a, unsigned parity) {
    asm volatile(
        "{\n\t.reg .pred P;\n"
        "MW_%=:\n\t"
        "mbarrier.try_wait.parity.acquire.cta.shared::cta.b64 P, [%0], %1, 0x989680;\n\t"
        "@P bra.uni MWD_%=;\n\t"
        "bra.uni MW_%=;\n"
        "MWD_%=:\n\t}"
        :: "r"(a), "r"(parity) : "memory");
}

// One CTA per batch element. Warp 0 runs the whole CTC forward DP in linear
// (probability) domain: lane l owns state pairs j=7l..7l+6 in registers.
// Per 6-step chunk: one mbarrier wait, 48 batched LDS into registers, then
// 6 pure-register steps (28 FADD/FMUL + 1 shfl each), one pow2 rescale.
// Warps 1-8 are producers: each owns ring slot (w-1) and chunks c==w-1 (mod 8),
// streams softmax probs (pre-divided by denom, label-masked) with a depth-2
// register prefetch, synced by full/empty mbarrier pairs (HW-sleep waits).
__global__ __launch_bounds__(NTH, 1)
void ctc_kernel(const float* __restrict__ attn,
                const int*   __restrict__ in_lens,
                const int*   __restrict__ out_lens,
                float*       __restrict__ out)
{
    __shared__ float s_p[NSLOT * CR][ROWF];
    __shared__ float s_pb[NSLOT * CR];
    __shared__ __align__(8) unsigned long long s_full[NSLOT], s_empty[NSLOT];
    __shared__ float s_fe[224], s_fo[224];

    const int b    = blockIdx.x;
    const int tid  = threadIdx.x;
    const int lane = tid & 31;
    const int w    = tid >> 5;
    const int L       = in_lens[b];    // 100..200
    const int out_len = out_lens[b];   // 700..900
    const float* attn_b = attn + (size_t)b * TQ * TK;
    const int nchunks = (out_len + CR - 1) / CR;

    // init: dead prob slots (k>=200) must read 0 forever; mbarriers count=32
    for (int i = tid; i < NSLOT * CR * ROWF; i += NTH) (&s_p[0][0])[i] = 0.f;
    if (tid < NSLOT) {
        mbar_init((unsigned)__cvta_generic_to_shared(&s_full[tid]), 32);
        mbar_init((unsigned)__cvta_generic_to_shared(&s_empty[tid]), 32);
    }
    __syncthreads();

    if (w > 0) {
        // ---------------- Producer warps (8); warp owns slot pw ----------
        const int pw = w - 1;
        const unsigned fbar = (unsigned)__cvta_generic_to_shared(&s_full[pw]);
        const unsigned ebar = (unsigned)__cvta_generic_to_shared(&s_empty[pw]);
        int kk[7]; bool kv[7];
        #pragma unroll
        for (int i = 0; i < 7; ++i) { kk[i] = lane + 32 * i; kv[i] = (kk[i] < TK); }

        // depth-2 rolling prefetch over this warp's row sequence
        float xA[7], xB[7];
        int tB = pw * CR + 1;
        {
            const float* rA = attn_b + (size_t)(pw * CR) * TK;
            const float* rB = attn_b + (size_t)tB * TK;
            #pragma unroll
            for (int i = 0; i < 7; ++i) {
                xA[i] = kv[i] ? __ldg(rA + kk[i]) : 0.f;
                xB[i] = kv[i] ? __ldg(rB + kk[i]) : 0.f;
            }
        }

        unsigned pe_phase = 1;                 // first empty-wait passes
        for (int c = pw; c < nchunks; c += NSLOT) {
            mbar_wait(ebar, pe_phase); pe_phase ^= 1;
            const int base = c * CR;
            #pragma unroll
            for (int r = 0; r < CR; ++r) {
                const int t = base + r;
                if (t >= out_len) break;
                float cur[7];
                #pragma unroll
                for (int i = 0; i < 7; ++i) cur[i] = xA[i];
                // rotate prefetch: xA<-xB, xB<-row after tB in our sequence
                {
                    const int tn = (tB % CR == CR - 1) ? tB + (NSLOT - 1) * CR + 1
                                                       : tB + 1;
                    #pragma unroll
                    for (int i = 0; i < 7; ++i) xA[i] = xB[i];
                    if (tn < out_len) {
                        const float* rn = attn_b + (size_t)tn * TK;
                        #pragma unroll
                        for (int i = 0; i < 7; ++i)
                            if (kv[i]) xB[i] = __ldg(rn + kk[i]);
                    }
                    tB = tn;
                }
                // softmax (pre-divided), label mask
                float e[7];
                float sum = 0.f;
                #pragma unroll
                for (int i = 0; i < 7; ++i) {
                    e[i] = kv[i] ? ex2f(cur[i] * LOG2E) : 0.f;
                    sum += e[i];
                }
                #pragma unroll
                for (int off = 16; off; off >>= 1)
                    sum += __shfl_xor_sync(0xffffffffu, sum, off);
                sum += EINV;                   // blank term once, post-reduce
                float rd = rcpf(sum);
                rd = rd * (2.0f - sum * rd);   // NR: near-exact 1/sum
                const int rr = pw * CR + r;
                #pragma unroll
                for (int i = 0; i < 7; ++i)
                    if (kv[i]) s_p[rr][kk[i]] = (kk[i] < L) ? e[i] * rd : 0.f;
                if (lane == 0) s_pb[rr] = EINV * rd;
            }
            __syncwarp();
            mbar_arrive(fbar);                 // all 32 lanes (count=32)
        }
    } else {
        // ---------------- DP warp ----------------------------------------
        float ae[7], ao[7];
        #pragma unroll
        for (int i = 0; i < 7; ++i) { ae[i] = 0.f; ao[i] = 0.f; }
        int C = 0;                             // stored = true * 2^C
        const int sbase = lane * 7;
        unsigned phase = 0;

        for (int c = 0; c < nchunks; ++c) {
            const int slot = c & (NSLOT - 1);
            mbar_wait((unsigned)__cvta_generic_to_shared(&s_full[slot]), phase);

            // batch-load the chunk's probs into registers (latency overlaps)
            float pv[CR][7], pbv[CR];
            #pragma unroll
            for (int r = 0; r < CR; ++r) {
                const int rr = slot * CR + r;
                pbv[r] = s_pb[rr];
                #pragma unroll
                for (int i = 0; i < 7; ++i) pv[r][i] = s_p[rr][sbase + i];
            }

            const int base = c * CR;
            const int nr = min(CR, out_len - base);
            #pragma unroll
            for (int r = 0; r < CR; ++r) {
                if (r < nr) {
                    if (c == 0 && r == 0) {    // t = 0 init
                        if (lane == 0) { ae[0] = pbv[0]; ao[0] = pv[0][0]; }
                        continue;
                    }
                    float a1in = __shfl_up_sync(0xffffffffu, ao[6], 1);
                    if (lane == 0) a1in = 0.f;
                    float tv[7];
                    tv[0] = ae[0] + a1in;
                    #pragma unroll
                    for (int i = 1; i < 7; ++i) tv[i] = ae[i] + ao[i - 1];
                    #pragma unroll
                    for (int i = 0; i < 7; ++i) {
                        ao[i] = (ao[i] + tv[i]) * pv[r][i];
                        ae[i] = tv[i] * pbv[r];
                    }
                }
            }
            mbar_arrive((unsigned)__cvta_generic_to_shared(&s_empty[slot]));
            if (slot == NSLOT - 1) phase ^= 1;

            // pow2 rescale once per chunk (growth <= 3^6 < 2^10: safe)
            float m = 0.f;
            #pragma unroll
            for (int i = 0; i < 7; ++i) m = fmaxf(m, fmaxf(ae[i], ao[i]));
            #pragma unroll
            for (int off = 16; off; off >>= 1)
                m = fmaxf(m, __shfl_xor_sync(0xffffffffu, m, off));
            if (m > 0.f) {
                const int eb = (__float_as_int(m) >> 23) & 255;
                int sh = 202 - eb;             // renormalize max to ~2^75
                sh = max(-120, min(120, sh));
                const float sc = __int_as_float((sh + 127) << 23);
                C += sh;
                #pragma unroll
                for (int i = 0; i < 7; ++i) { ae[i] *= sc; ao[i] *= sc; }
            }
        }

        // fin = alpha at t=out_len-1; hi=fin[2L] (even of pair L),
        // lo=fin[2L-1] (odd of pair L-1)
        #pragma unroll
        for (int i = 0; i < 7; ++i) {
            s_fe[lane * 7 + i] = ae[i];
            s_fo[lane * 7 + i] = ao[i];
        }
        __syncwarp();
        if (lane == 0) {
            const float hi = s_fe[L];
            const float lo = s_fo[L - 1];
            float loss = -(lg2f(hi + lo) - (float)C) * LN2;
            if (!(loss < 1e20f)) loss = 0.0f;  // inf/NaN/huge -> 0 (ref rule)
            g_losses[b] = loss / (float)L;
            __threadfence();
            const int n = atomicAdd(&g_cnt, 1);
            if (n == BATCH - 1) {              // last CTA: deterministic mean
                __threadfence();
                float s = 0.f;
                for (int i = 0; i < BATCH; ++i) s += g_losses[i];
                out[0] = s * (1.0f / BATCH);
                g_cnt = 0;                     // reset for graph replay
                __threadfence();
            }
        }
    }
}

extern "C" void kernel_launch(void* const* d_in, const int* in_sizes, int n_in,
                              void* d_out, int out_size)
{
    const float* attn     = (const float*)d_in[0];
    const int*   in_lens  = (const int*)d_in[1];
    const int*   out_lens = (const int*)d_in[2];
    (void)in_sizes; (void)n_in; (void)out_size;

    ctc_kernel<<<BATCH, NTH>>>(attn, in_lens, out_lens, (float*)d_out);
}

// round 10
// speedup vs baseline: 2.1813x; 1.2209x over previous
#include <cuda_runtime.h>

#define TQ     900
#define TK     200
#define BATCH  128
#define LOG2E  1.4426950408889634f
#define LN2    0.6931471805599453f
#define EINV   0.36787944117144233f   // exp(-1): blank prob numerator
#define NTH    544                    // 1 DP warp + 16 producer warps
#define CR     8                      // rows per chunk
#define NSLOT  8                      // ring slots
#define ROWF   256                    // floats per ring row (split-f4 layout)
#define RING_BYTES (NSLOT * CR * ROWF * 4)   // 64 KB dynamic smem

__device__ float g_losses[BATCH];
__device__ int   g_cnt = 0;

__device__ __forceinline__ float ex2f(float x) {
    float y; asm("ex2.approx.ftz.f32 %0, %1;" : "=f"(y) : "f"(x)); return y;
}
__device__ __forceinline__ float lg2f(float x) {
    float y; asm("lg2.approx.ftz.f32 %0, %1;" : "=f"(y) : "f"(x)); return y;
}
__device__ __forceinline__ float rcpf(float x) {
    float y; asm("rcp.approx.ftz.f32 %0, %1;" : "=f"(y) : "f"(x)); return y;
}
__device__ __forceinline__ unsigned redux_max_u32(unsigned v) {
    unsigned r; asm("redux.sync.max.u32 %0, %1, 0xffffffff;" : "=r"(r) : "r"(v));
    return r;
}
__device__ __forceinline__ void mbar_init(unsigned a, unsigned cnt) {
    asm volatile("mbarrier.init.shared.b64 [%0], %1;" :: "r"(a), "r"(cnt) : "memory");
}
__device__ __forceinline__ void mbar_arrive(unsigned a) {
    asm volatile("mbarrier.arrive.release.cta.shared::cta.b64 _, [%0];" :: "r"(a) : "memory");
}
__device__ __forceinline__ void mbar_wait(unsigned a, unsigned parity) {
    asm volatile(
        "{\n\t.reg .pred P;\n"
        "MW_%=:\n\t"
        "mbarrier.try_wait.parity.acquire.cta.shared::cta.b64 P, [%0], %1, 0x989680;\n\t"
        "@P bra.uni MWD_%=;\n\t"
        "bra.uni MW_%=;\n"
        "MWD_%=:\n\t}"
        :: "r"(a), "r"(parity) : "memory");
}

// One CTA per batch element. Warp 0 runs the whole CTC forward DP in linear
// (probability) domain: lane l owns state pairs j=7l..7l+6 in registers.
// Ring row layout (256 floats): [lane*4 + i] holds probs p0..p3 of DP lane,
// [128 + lane*4 + i] holds p4..p6 and (pad slot i=3) the blank prob pb —
// so the DP reads each row with two conflict-free LDS.128.
// Warps 1..16: two producer warps per ring slot; each batch-loads its 4 rows'
// logits up-front (full MLP), computes pre-divided label-masked softmax probs,
// stores, and arrives on the slot's full mbarrier (count 64). DP arrives on
// empty (count 32). Underflow handled by per-chunk pow2 rescale via
// redux.sync (positive floats compare as u32), exponent accumulator C.
__global__ __launch_bounds__(NTH, 1)
void ctc_kernel(const float* __restrict__ attn,
                const int*   __restrict__ in_lens,
                const int*   __restrict__ out_lens,
                float*       __restrict__ out)
{
    extern __shared__ __align__(16) float ring[];
    __shared__ __align__(8) unsigned long long s_full[NSLOT], s_empty[NSLOT];
    __shared__ float s_fe[224], s_fo[224];

    const int b    = blockIdx.x;
    const int tid  = threadIdx.x;
    const int lane = tid & 31;
    const int w    = tid >> 5;
    const int L       = in_lens[b];    // 100..200
    const int out_len = out_lens[b];   // 700..900
    const float* attn_b = attn + (size_t)b * TQ * TK;
    const int nchunks = (out_len + CR - 1) / CR;

    // init: unwritten prob slots must read 0 forever
    for (int i = tid; i < NSLOT * CR * ROWF; i += NTH) ring[i] = 0.f;
    if (tid < NSLOT) {
        mbar_init((unsigned)__cvta_generic_to_shared(&s_full[tid]), 64);
        mbar_init((unsigned)__cvta_generic_to_shared(&s_empty[tid]), 32);
    }
    __syncthreads();

    if (w > 0) {
        // ---------------- Producer warps (16): 2 per slot -----------------
        const int p2   = w - 1;
        const int slot = p2 >> 1;
        const int half = p2 & 1;
        const unsigned fb = (unsigned)__cvta_generic_to_shared(&s_full[slot]);
        const unsigned eb = (unsigned)__cvta_generic_to_shared(&s_empty[slot]);

        int kk[7], widx[7]; bool kv[7];
        #pragma unroll
        for (int i = 0; i < 7; ++i) {
            kk[i] = lane + 32 * i;
            kv[i] = (kk[i] < TK);
            const int dpl = kk[i] / 7, q = kk[i] % 7;
            widx[i] = (q < 4) ? (dpl * 4 + q) : (128 + dpl * 4 + (q - 4));
        }
        const int pbidx = 128 + lane * 4 + 3;   // pad slot: pb for DP lane==lane

        unsigned pe = 1;                         // first empty-wait passes
        for (int c = slot; c < nchunks; c += NSLOT) {
            mbar_wait(eb, pe); pe ^= 1;
            const int base = c * CR + half * 4;

            // batch-load 4 rows x 7 logits (28 LDG in flight)
            float x[4][7];
            #pragma unroll
            for (int r = 0; r < 4; ++r) {
                const int t = base + r;
                if (t < out_len) {
                    const float* row = attn_b + (size_t)t * TK;
                    #pragma unroll
                    for (int i = 0; i < 7; ++i)
                        x[r][i] = kv[i] ? __ldg(row + kk[i]) : 0.f;
                }
            }
            #pragma unroll
            for (int r = 0; r < 4; ++r) {
                const int t = base + r;
                if (t >= out_len) break;
                float e[7];
                float sum = 0.f;
                #pragma unroll
                for (int i = 0; i < 7; ++i) {
                    e[i] = kv[i] ? ex2f(x[r][i] * LOG2E) : 0.f;
                    sum += e[i];
                }
                #pragma unroll
                for (int off = 16; off; off >>= 1)
                    sum += __shfl_xor_sync(0xffffffffu, sum, off);
                sum += EINV;                     // blank term once, post-reduce
                float rd = rcpf(sum);
                rd = rd * (2.0f - sum * rd);     // NR: near-exact 1/sum
                float* rowp = ring + (size_t)(slot * CR + half * 4 + r) * ROWF;
                #pragma unroll
                for (int i = 0; i < 7; ++i)
                    if (kv[i]) rowp[widx[i]] = (kk[i] < L) ? e[i] * rd : 0.f;
                rowp[pbidx] = EINV * rd;         // every lane writes its pad
            }
            mbar_arrive(fb);                     // release: orders the stores
        }
    } else {
        // ---------------- DP warp ----------------------------------------
        float ae[7], ao[7];
        #pragma unroll
        for (int i = 0; i < 7; ++i) { ae[i] = 0.f; ao[i] = 0.f; }
        int C = 0;                               // stored = true * 2^C
        unsigned ph = 0;

        for (int c = 0; c < nchunks; ++c) {
            const int slot = c & (NSLOT - 1);
            mbar_wait((unsigned)__cvta_generic_to_shared(&s_full[slot]), ph);
            const float* rb = ring + (size_t)slot * CR * ROWF;

            // depth-2 rolling float4 loads (conflict-free LDS.128)
            float4 A0 = *(const float4*)(rb + lane * 4);
            float4 B0 = *(const float4*)(rb + 128 + lane * 4);
            float4 A1 = *(const float4*)(rb + ROWF + lane * 4);
            float4 B1 = *(const float4*)(rb + ROWF + 128 + lane * 4);

            const int nr = min(CR, out_len - c * CR);
            #pragma unroll
            for (int r = 0; r < CR; ++r) {
                if (r < nr) {
                    const float4 a  = A0;
                    const float4 bv = B0;
                    A0 = A1; B0 = B1;
                    if (r + 2 < CR) {
                        A1 = *(const float4*)(rb + (r + 2) * ROWF + lane * 4);
                        B1 = *(const float4*)(rb + (r + 2) * ROWF + 128 + lane * 4);
                    }
                    if (c == 0 && r == 0) {      // t = 0 init
                        if (lane == 0) { ae[0] = bv.w; ao[0] = a.x; }
                        continue;
                    }
                    float a1in = __shfl_up_sync(0xffffffffu, ao[6], 1);
                    if (lane == 0) a1in = 0.f;
                    float tv[7];
                    tv[0] = ae[0] + a1in;
                    #pragma unroll
                    for (int i = 1; i < 7; ++i) tv[i] = ae[i] + ao[i - 1];
                    const float pb = bv.w;
                    ao[0] = (ao[0] + tv[0]) * a.x;
                    ao[1] = (ao[1] + tv[1]) * a.y;
                    ao[2] = (ao[2] + tv[2]) * a.z;
                    ao[3] = (ao[3] + tv[3]) * a.w;
                    ao[4] = (ao[4] + tv[4]) * bv.x;
                    ao[5] = (ao[5] + tv[5]) * bv.y;
                    ao[6] = (ao[6] + tv[6]) * bv.z;
                    #pragma unroll
                    for (int i = 0; i < 7; ++i) ae[i] = tv[i] * pb;
                }
            }
            mbar_arrive((unsigned)__cvta_generic_to_shared(&s_empty[slot]));
            if (slot == NSLOT - 1) ph ^= 1;

            // pow2 rescale once per chunk (redux over positive-float bits)
            float m = 0.f;
            #pragma unroll
            for (int i = 0; i < 7; ++i) m = fmaxf(m, fmaxf(ae[i], ao[i]));
            m = __uint_as_float(redux_max_u32(__float_as_uint(m)));
            if (m > 0.f) {
                const int ebx = (__float_as_int(m) >> 23) & 255;
                int sh = 217 - ebx;              // renormalize max to ~2^90
                sh = max(-120, min(120, sh));
                const float sc = __int_as_float((sh + 127) << 23);
                C += sh;
                #pragma unroll
                for (int i = 0; i < 7; ++i) { ae[i] *= sc; ao[i] *= sc; }
            }
        }

        // fin = alpha at t=out_len-1; hi=fin[2L] (even of pair L),
        // lo=fin[2L-1] (odd of pair L-1)
        #pragma unroll
        for (int i = 0; i < 7; ++i) {
            s_fe[lane * 7 + i] = ae[i];
            s_fo[lane * 7 + i] = ao[i];
        }
        __syncwarp();
        if (lane == 0) {
            const float hi = s_fe[L];
            const float lo = s_fo[L - 1];
            float loss = -(lg2f(hi + lo) - (float)C) * LN2;
            if (!(loss < 1e20f)) loss = 0.0f;    // inf/NaN/huge -> 0 (ref rule)
            g_losses[b] = loss / (float)L;
            __threadfence();
            const int n = atomicAdd(&g_cnt, 1);
            if (n == BATCH - 1) {                // last CTA: deterministic mean
                __threadfence();
                float s = 0.f;
                for (int i = 0; i < BATCH; ++i) s += g_losses[i];
                out[0] = s * (1.0f / BATCH);
                g_cnt = 0;                       // reset for graph replay
                __threadfence();
            }
        }
    }
}

extern "C" void kernel_launch(void* const* d_in, const int* in_sizes, int n_in,
                              void* d_out, int out_size)
{
    const float* attn     = (const float*)d_in[0];
    const int*   in_lens  = (const int*)d_in[1];
    const int*   out_lens = (const int*)d_in[2];
    (void)in_sizes; (void)n_in; (void)out_size;

    cudaFuncSetAttribute(ctc_kernel,
                         cudaFuncAttributeMaxDynamicSharedMemorySize, RING_BYTES);
    ctc_kernel<<<BATCH, NTH, RING_BYTES>>>(attn, in_lens, out_lens, (float*)d_out);
}

// round 12
// speedup vs baseline: 2.2332x; 1.0238x over previous
#include <cuda_runtime.h>

#define TQ     900
#define TK     200
#define BATCH  128
#define LOG2E  1.4426950408889634f
#define LN2    0.6931471805599453f
#define EINV   0.36787944117144233f   // exp(-1): blank prob numerator
#define NTH    544                    // 16 producer warps + 1 DP warp (highest wid)
#define DPW    16                     // DP warp id: HIGHEST wid -> top arbiter priority
#define CR     8                      // rows per chunk
#define NSLOT  8                      // ring slots
#define ROWF   256                    // floats per ring row (split-f4 layout)
#define RING_BYTES (NSLOT * CR * ROWF * 4)   // 64 KB dynamic smem

__device__ float g_losses[BATCH];
__device__ int   g_cnt = 0;

__device__ __forceinline__ float ex2f(float x) {
    float y; asm("ex2.approx.ftz.f32 %0, %1;" : "=f"(y) : "f"(x)); return y;
}
__device__ __forceinline__ float lg2f(float x) {
    float y; asm("lg2.approx.ftz.f32 %0, %1;" : "=f"(y) : "f"(x)); return y;
}
__device__ __forceinline__ float rcpf(float x) {
    float y; asm("rcp.approx.ftz.f32 %0, %1;" : "=f"(y) : "f"(x)); return y;
}
__device__ __forceinline__ unsigned redux_max_u32(unsigned v) {
    unsigned r; asm("redux.sync.max.u32 %0, %1, 0xffffffff;" : "=r"(r) : "r"(v));
    return r;
}
__device__ __forceinline__ void mbar_init(unsigned a, unsigned cnt) {
    asm volatile("mbarrier.init.shared.b64 [%0], %1;" :: "r"(a), "r"(cnt) : "memory");
}
__device__ __forceinline__ void mbar_arrive(unsigned a) {
    asm volatile("mbarrier.arrive.release.cta.shared::cta.b64 _, [%0];" :: "r"(a) : "memory");
}
__device__ __forceinline__ void mbar_wait(unsigned a, unsigned parity) {
    asm volatile(
        "{\n\t.reg .pred P;\n"
        "MW_%=:\n\t"
        "mbarrier.try_wait.parity.acquire.cta.shared::cta.b64 P, [%0], %1, 0x989680;\n\t"
        "@P bra.uni MWD_%=;\n\t"
        "bra.uni MW_%=;\n"
        "MWD_%=:\n\t}"
        :: "r"(a), "r"(parity) : "memory");
}

// One CTA per batch element. Warp DPW (=16, the HIGHEST wid -> wins the
// hi-wid-first issue arbiter on its SMSP) runs the whole CTC forward DP in
// linear (probability) domain: lane l owns state pairs j=7l..7l+6 in regs.
// Ring row layout (256 floats): [lane*4+i] = probs p0..p3 of DP lane l,
// [128+lane*4+i] = p4..p6 and (pad i=3) the blank prob pb — two conflict-free
// LDS.128 per row. Warps 0..15: two producer warps per ring slot; each
// batch-loads its 4 rows' logits up-front (full MLP), computes pre-divided
// label-masked softmax probs, stores, arrives on the slot's full mbarrier
// (count 64). DP arrives on empty (count 32). Underflow handled by per-chunk
// pow2 rescale via redux.sync (positive floats compare as u32), exponent C.
__global__ __launch_bounds__(NTH, 1)
void ctc_kernel(const float* __restrict__ attn,
                const int*   __restrict__ in_lens,
                const int*   __restrict__ out_lens,
                float*       __restrict__ out)
{
    extern __shared__ __align__(16) float ring[];
    __shared__ __align__(8) unsigned long long s_full[NSLOT], s_empty[NSLOT];
    __shared__ float s_fe[224], s_fo[224];

    const int b    = blockIdx.x;
    const int tid  = threadIdx.x;
    const int lane = tid & 31;
    const int w    = tid >> 5;
    const int L       = in_lens[b];    // 100..200
    const int out_len = out_lens[b];   // 700..900
    const float* attn_b = attn + (size_t)b * TQ * TK;
    const int nchunks = (out_len + CR - 1) / CR;

    // init: unwritten prob slots must read 0 forever
    for (int i = tid; i < NSLOT * CR * ROWF; i += NTH) ring[i] = 0.f;
    if (tid < NSLOT) {
        mbar_init((unsigned)__cvta_generic_to_shared(&s_full[tid]), 64);
        mbar_init((unsigned)__cvta_generic_to_shared(&s_empty[tid]), 32);
    }
    __syncthreads();

    if (w < DPW) {
        // ---------------- Producer warps (16): 2 per slot -----------------
        const int slot = w >> 1;
        const int half = w & 1;
        const unsigned fb = (unsigned)__cvta_generic_to_shared(&s_full[slot]);
        const unsigned eb = (unsigned)__cvta_generic_to_shared(&s_empty[slot]);

        int kk[7], widx[7]; bool kv[7];
        #pragma unroll
        for (int i = 0; i < 7; ++i) {
            kk[i] = lane + 32 * i;
            kv[i] = (kk[i] < TK);
            const int dpl = kk[i] / 7, q = kk[i] % 7;
            widx[i] = (q < 4) ? (dpl * 4 + q) : (128 + dpl * 4 + (q - 4));
        }
        const int pbidx = 128 + lane * 4 + 3;   // pad slot: pb for DP lane==lane

        unsigned pe = 1;                         // first empty-wait passes
        for (int c = slot; c < nchunks; c += NSLOT) {
            mbar_wait(eb, pe); pe ^= 1;
            const int base = c * CR + half * 4;

            // batch-load 4 rows x 7 logits (28 LDG in flight)
            float x[4][7];
            #pragma unroll
            for (int r = 0; r < 4; ++r) {
                const int t = base + r;
                if (t < out_len) {
                    const float* row = attn_b + (size_t)t * TK;
                    #pragma unroll
                    for (int i = 0; i < 7; ++i)
                        x[r][i] = kv[i] ? __ldg(row + kk[i]) : 0.f;
                }
            }
            #pragma unroll
            for (int r = 0; r < 4; ++r) {
                const int t = base + r;
                if (t >= out_len) break;
                float e[7];
                float sum = 0.f;
                #pragma unroll
                for (int i = 0; i < 7; ++i) {
                    e[i] = kv[i] ? ex2f(x[r][i] * LOG2E) : 0.f;
                    sum += e[i];
                }
                #pragma unroll
                for (int off = 16; off; off >>= 1)
                    sum += __shfl_xor_sync(0xffffffffu, sum, off);
                sum += EINV;                     // blank term once, post-reduce
                float rd = rcpf(sum);
                rd = rd * (2.0f - sum * rd);     // NR: near-exact 1/sum
                float* rowp = ring + (size_t)(slot * CR + half * 4 + r) * ROWF;
                #pragma unroll
                for (int i = 0; i < 7; ++i)
                    if (kv[i]) rowp[widx[i]] = (kk[i] < L) ? e[i] * rd : 0.f;
                rowp[pbidx] = EINV * rd;         // every lane writes its pad
            }
            mbar_arrive(fb);                     // release: orders the stores
        }
    } else {
        // ---------------- DP warp (wid 16: top arbiter priority) ----------
        float ae[7], ao[7];
        #pragma unroll
        for (int i = 0; i < 7; ++i) { ae[i] = 0.f; ao[i] = 0.f; }
        int C = 0;                               // stored = true * 2^C
        unsigned ph = 0;

        for (int c = 0; c < nchunks; ++c) {
            const int slot = c & (NSLOT - 1);
            mbar_wait((unsigned)__cvta_generic_to_shared(&s_full[slot]), ph);
            const float* rb = ring + (size_t)slot * CR * ROWF;

            // depth-2 rolling float4 loads (conflict-free LDS.128)
            float4 A0 = *(const float4*)(rb + lane * 4);
            float4 B0 = *(const float4*)(rb + 128 + lane * 4);
            float4 A1 = *(const float4*)(rb + ROWF + lane * 4);
            float4 B1 = *(const float4*)(rb + ROWF + 128 + lane * 4);

            const int nr = min(CR, out_len - c * CR);
            #pragma unroll
            for (int r = 0; r < CR; ++r) {
                if (r < nr) {
                    const float4 a  = A0;
                    const float4 bv = B0;
                    A0 = A1; B0 = B1;
                    if (r + 2 < CR) {
                        A1 = *(const float4*)(rb + (r + 2) * ROWF + lane * 4);
                        B1 = *(const float4*)(rb + (r + 2) * ROWF + 128 + lane * 4);
                    }
                    if (c == 0 && r == 0) {      // t = 0 init
                        if (lane == 0) { ae[0] = bv.w; ao[0] = a.x; }
                        continue;
                    }
                    float a1in = __shfl_up_sync(0xffffffffu, ao[6], 1);
                    if (lane == 0) a1in = 0.f;
                    float tv[7];
                    tv[0] = ae[0] + a1in;
                    #pragma unroll
                    for (int i = 1; i < 7; ++i) tv[i] = ae[i] + ao[i - 1];
                    const float pb = bv.w;
                    ao[0] = (ao[0] + tv[0]) * a.x;
                    ao[1] = (ao[1] + tv[1]) * a.y;
                    ao[2] = (ao[2] + tv[2]) * a.z;
                    ao[3] = (ao[3] + tv[3]) * a.w;
                    ao[4] = (ao[4] + tv[4]) * bv.x;
                    ao[5] = (ao[5] + tv[5]) * bv.y;
                    ao[6] = (ao[6] + tv[6]) * bv.z;
                    #pragma unroll
                    for (int i = 0; i < 7; ++i) ae[i] = tv[i] * pb;
                }
            }
            mbar_arrive((unsigned)__cvta_generic_to_shared(&s_empty[slot]));
            if (slot == NSLOT - 1) ph ^= 1;

            // pow2 rescale once per chunk (redux over positive-float bits)
            float m = 0.f;
            #pragma unroll
            for (int i = 0; i < 7; ++i) m = fmaxf(m, fmaxf(ae[i], ao[i]));
            m = __uint_as_float(redux_max_u32(__float_as_uint(m)));
            if (m > 0.f) {
                const int ebx = (__float_as_int(m) >> 23) & 255;
                int sh = 217 - ebx;              // renormalize max to ~2^90
                sh = max(-120, min(120, sh));
                const float sc = __int_as_float((sh + 127) << 23);
                C += sh;
                #pragma unroll
                for (int i = 0; i < 7; ++i) { ae[i] *= sc; ao[i] *= sc; }
            }
        }

        // fin = alpha at t=out_len-1; hi=fin[2L] (even of pair L),
        // lo=fin[2L-1] (odd of pair L-1)
        #pragma unroll
        for (int i = 0; i < 7; ++i) {
            s_fe[lane * 7 + i] = ae[i];
            s_fo[lane * 7 + i] = ao[i];
        }
        __syncwarp();
        if (lane == 0) {
            const float hi = s_fe[L];
            const float lo = s_fo[L - 1];
            float loss = -(lg2f(hi + lo) - (float)C) * LN2;
            if (!(loss < 1e20f)) loss = 0.0f;    // inf/NaN/huge -> 0 (ref rule)
            g_losses[b] = loss / (float)L;
            __threadfence();
            const int n = atomicAdd(&g_cnt, 1);
            if (n == BATCH - 1) {                // last CTA: deterministic mean
                __threadfence();
                float s = 0.f;
                for (int i = 0; i < BATCH; ++i) s += g_losses[i];
                out[0] = s * (1.0f / BATCH);
                g_cnt = 0;                       // reset for graph replay
                __threadfence();
            }
        }
    }
}

extern "C" void kernel_launch(void* const* d_in, const int* in_sizes, int n_in,
                              void* d_out, int out_size)
{
    const float* attn     = (const float*)d_in[0];
    const int*   in_lens  = (const int*)d_in[1];
    const int*   out_lens = (const int*)d_in[2];
    (void)in_sizes; (void)n_in; (void)out_size;

    cudaFuncSetAttribute(ctc_kernel,
                         cudaFuncAttributeMaxDynamicSharedMemorySize, RING_BYTES);
    ctc_kernel<<<BATCH, NTH, RING_BYTES>>>(attn, in_lens, out_lens, (float*)d_out);
}

// round 15
// speedup vs baseline: 2.2356x; 1.0011x over previous
#include <cuda_runtime.h>

#define TQ     900
#define TK     200
#define BATCH  128
#define LOG2E  1.4426950408889634f
#define LN2    0.6931471805599453f
#define EINV   0.36787944117144233f   // exp(-1): blank prob numerator
#define NTH    544                    // 16 producer warps + 1 DP warp (highest wid)
#define DPW    16
#define CR     16                     // rows per chunk
#define NSLOT  4                      // ring slots (64 rows total)
#define ROWF   256                    // floats per ring row (split-f4 layout)
#define RING_BYTES (NSLOT * CR * ROWF * 4)   // 64 KB dynamic smem

__device__ float g_losses[BATCH];
__device__ int   g_cnt = 0;

__device__ __forceinline__ float ex2f(float x) {
    float y; asm("ex2.approx.ftz.f32 %0, %1;" : "=f"(y) : "f"(x)); return y;
}
__device__ __forceinline__ float lg2f(float x) {
    float y; asm("lg2.approx.ftz.f32 %0, %1;" : "=f"(y) : "f"(x)); return y;
}
__device__ __forceinline__ float rcpf(float x) {
    float y; asm("rcp.approx.ftz.f32 %0, %1;" : "=f"(y) : "f"(x)); return y;
}
__device__ __forceinline__ unsigned redux_max_u32(unsigned v) {
    unsigned r; asm("redux.sync.max.u32 %0, %1, 0xffffffff;" : "=r"(r) : "r"(v));
    return r;
}
__device__ __forceinline__ void mbar_init(unsigned a, unsigned cnt) {
    asm volatile("mbarrier.init.shared.b64 [%0], %1;" :: "r"(a), "r"(cnt) : "memory");
}
__device__ __forceinline__ void mbar_arrive(unsigned a) {
    asm volatile("mbarrier.arrive.release.cta.shared::cta.b64 _, [%0];" :: "r"(a) : "memory");
}
__device__ __forceinline__ void mbar_wait(unsigned a, unsigned parity) {
    asm volatile(
        "{\n\t.reg .pred P;\n"
        "MW_%=:\n\t"
        "mbarrier.try_wait.parity.acquire.cta.shared::cta.b64 P, [%0], %1, 0x989680;\n\t"
        "@P bra.uni MWD_%=;\n\t"
        "bra.uni MW_%=;\n"
        "MWD_%=:\n\t}"
        :: "r"(a), "r"(parity) : "memory");
}

// One CTA per batch element. Warp 16 (highest wid) runs the whole CTC forward
// DP in linear (probability) domain: lane l owns state pairs j=7l..7l+6 in
// registers. Per 16-row chunk: one mbarrier wait, rolling conflict-free
// LDS.128 loads, 16 steps of 28 FADD/FMUL + 1 shfl (issued first; latency
// hidden under pair-1..6 math). Rescale every 8 rows (NOT per chunk): pow2
// renormalize max to ~2^90 via redux.sync over positive-float bits; 16-step
// intervals underflow (worst-case decay ~2^-10/step -> 2^-160), 8-step is the
// R12-proven safe interval. Warps 0..15: four producer warps per ring slot
// (4 rows each); batch-load 28 logits up-front, pre-divided label-masked
// softmax probs in split-f4 layout, full mbar count 128; DP arrives empty (32).
__global__ __launch_bounds__(NTH, 1)
void ctc_kernel(const float* __restrict__ attn,
                const int*   __restrict__ in_lens,
                const int*   __restrict__ out_lens,
                float*       __restrict__ out)
{
    extern __shared__ __align__(16) float ring[];
    __shared__ __align__(8) unsigned long long s_full[NSLOT], s_empty[NSLOT];
    __shared__ float s_fe[224], s_fo[224];

    const int b    = blockIdx.x;
    const int tid  = threadIdx.x;
    const int lane = tid & 31;
    const int w    = tid >> 5;
    const int L       = in_lens[b];    // 100..200
    const int out_len = out_lens[b];   // 700..900
    const float* attn_b = attn + (size_t)b * TQ * TK;
    const int nchunks = (out_len + CR - 1) / CR;

    // init: unwritten prob slots must read 0 forever
    for (int i = tid; i < NSLOT * CR * ROWF; i += NTH) ring[i] = 0.f;
    if (tid < NSLOT) {
        mbar_init((unsigned)__cvta_generic_to_shared(&s_full[tid]), 128);
        mbar_init((unsigned)__cvta_generic_to_shared(&s_empty[tid]), 32);
    }
    __syncthreads();

    if (w < DPW) {
        // ------------- Producer warps (16): 4 per slot, 4 rows each -------
        const int slot = w >> 2;
        const int quar = w & 3;
        const unsigned fb = (unsigned)__cvta_generic_to_shared(&s_full[slot]);
        const unsigned eb = (unsigned)__cvta_generic_to_shared(&s_empty[slot]);

        int kk[7], widx[7]; bool kv[7];
        #pragma unroll
        for (int i = 0; i < 7; ++i) {
            kk[i] = lane + 32 * i;
            kv[i] = (kk[i] < TK);
            const int dpl = kk[i] / 7, q = kk[i] % 7;
            widx[i] = (q < 4) ? (dpl * 4 + q) : (128 + dpl * 4 + (q - 4));
        }
        const int pbidx = 128 + lane * 4 + 3;   // pad slot: pb for DP lane==lane

        unsigned pe = 1;                         // first empty-wait passes
        for (int c = slot; c < nchunks; c += NSLOT) {
            mbar_wait(eb, pe); pe ^= 1;
            const int base = c * CR + quar * 4;

            // batch-load 4 rows x 7 logits (28 LDG in flight)
            float x[4][7];
            #pragma unroll
            for (int r = 0; r < 4; ++r) {
                const int t = base + r;
                if (t < out_len) {
                    const float* row = attn_b + (size_t)t * TK;
                    #pragma unroll
                    for (int i = 0; i < 7; ++i)
                        x[r][i] = kv[i] ? __ldg(row + kk[i]) : 0.f;
                }
            }
            #pragma unroll
            for (int r = 0; r < 4; ++r) {
                const int t = base + r;
                if (t >= out_len) break;
                float e[7];
                float sum = 0.f;
                #pragma unroll
                for (int i = 0; i < 7; ++i) {
                    e[i] = kv[i] ? ex2f(x[r][i] * LOG2E) : 0.f;
                    sum += e[i];
                }
                #pragma unroll
                for (int off = 16; off; off >>= 1)
                    sum += __shfl_xor_sync(0xffffffffu, sum, off);
                sum += EINV;                     // blank term once, post-reduce
                float rd = rcpf(sum);
                rd = rd * (2.0f - sum * rd);     // NR: near-exact 1/sum
                float* rowp = ring + (size_t)(slot * CR + quar * 4 + r) * ROWF;
                #pragma unroll
                for (int i = 0; i < 7; ++i)
                    if (kv[i]) rowp[widx[i]] = (kk[i] < L) ? e[i] * rd : 0.f;
                rowp[pbidx] = EINV * rd;         // every lane writes its pad
            }
            mbar_arrive(fb);                     // release: orders the stores
        }
    } else {
        // ------------- DP warp (wid 16) -----------------------------------
        float ae[7], ao[7];
        #pragma unroll
        for (int i = 0; i < 7; ++i) { ae[i] = 0.f; ao[i] = 0.f; }
        int C = 0;                               // stored = true * 2^C
        unsigned ph = 0;

        for (int c = 0; c < nchunks; ++c) {
            const int slot = c & (NSLOT - 1);
            mbar_wait((unsigned)__cvta_generic_to_shared(&s_full[slot]), ph);
            const float* rb = ring + (size_t)slot * CR * ROWF;

            // depth-2 rolling float4 loads (conflict-free LDS.128)
            float4 A0 = *(const float4*)(rb + lane * 4);
            float4 B0 = *(const float4*)(rb + 128 + lane * 4);
            float4 A1 = *(const float4*)(rb + ROWF + lane * 4);
            float4 B1 = *(const float4*)(rb + ROWF + 128 + lane * 4);

            const int nr = min(CR, out_len - c * CR);
            #pragma unroll
            for (int r = 0; r < CR; ++r) {
                if (r < nr) {
                    const float4 a  = A0;
                    const float4 bv = B0;
                    A0 = A1; B0 = B1;
                    if (r + 2 < CR) {
                        A1 = *(const float4*)(rb + (r + 2) * ROWF + lane * 4);
                        B1 = *(const float4*)(rb + (r + 2) * ROWF + 128 + lane * 4);
                    }
                    if (c == 0 && r == 0) {      // t = 0 init
                        if (lane == 0) { ae[0] = bv.w; ao[0] = a.x; }
                        continue;
                    }
                    // shfl FIRST; its latency hides under pairs 1..6 math
                    float a1in = __shfl_up_sync(0xffffffffu, ao[6], 1);
                    const float pb = bv.w;
                    float tv1 = ae[1] + ao[0];
                    float tv2 = ae[2] + ao[1];
                    float tv3 = ae[3] + ao[2];
                    float tv4 = ae[4] + ao[3];
                    float tv5 = ae[5] + ao[4];
                    float tv6 = ae[6] + ao[5];
                    ao[1] = (ao[1] + tv1) * a.y;   ae[1] = tv1 * pb;
                    ao[2] = (ao[2] + tv2) * a.z;   ae[2] = tv2 * pb;
                    ao[3] = (ao[3] + tv3) * a.w;   ae[3] = tv3 * pb;
                    ao[4] = (ao[4] + tv4) * bv.x;  ae[4] = tv4 * pb;
                    ao[5] = (ao[5] + tv5) * bv.y;  ae[5] = tv5 * pb;
                    ao[6] = (ao[6] + tv6) * bv.z;  ae[6] = tv6 * pb;
                    if (lane == 0) a1in = 0.f;
                    float tv0 = ae[0] + a1in;
                    ao[0] = (ao[0] + tv0) * a.x;   ae[0] = tv0 * pb;
                }

                // rescale every 8 rows (r==7 and r==15): renormalize max to
                // ~2^90 (branchless; redux over positive-float bits)
                if ((r & 7) == 7) {
                    float m = 0.f;
                    #pragma unroll
                    for (int i = 0; i < 7; ++i) m = fmaxf(m, fmaxf(ae[i], ao[i]));
                    m = __uint_as_float(redux_max_u32(__float_as_uint(m)));
                    const int ebx = (__float_as_int(m) >> 23) & 255;
                    int sh = 217 - ebx;
                    sh = max(-120, min(120, sh));
                    const float sc = __int_as_float((sh + 127) << 23);
                    C += sh;
                    #pragma unroll
                    for (int i = 0; i < 7; ++i) { ae[i] *= sc; ao[i] *= sc; }
                }
            }
            mbar_arrive((unsigned)__cvta_generic_to_shared(&s_empty[slot]));
            if (slot == NSLOT - 1) ph ^= 1;
        }

        // fin = alpha at t=out_len-1; hi=fin[2L] (even of pair L),
        // lo=fin[2L-1] (odd of pair L-1)
        #pragma unroll
        for (int i = 0; i < 7; ++i) {
            s_fe[lane * 7 + i] = ae[i];
            s_fo[lane * 7 + i] = ao[i];
        }
        __syncwarp();
        if (lane == 0) {
            const float hi = s_fe[L];
            const float lo = s_fo[L - 1];
            float loss = -(lg2f(hi + lo) - (float)C) * LN2;
            if (!(loss < 1e20f)) loss = 0.0f;    // inf/NaN/huge -> 0 (ref rule)
            g_losses[b] = loss / (float)L;
            __threadfence();
            const int n = atomicAdd(&g_cnt, 1);
            if (n == BATCH - 1) {                // last CTA: deterministic mean
                __threadfence();
                float s = 0.f;
                for (int i = 0; i < BATCH; ++i) s += g_losses[i];
                out[0] = s * (1.0f / BATCH);
                g_cnt = 0;                       // reset for graph replay
                __threadfence();
            }
        }
    }
}

extern "C" void kernel_launch(void* const* d_in, const int* in_sizes, int n_in,
                              void* d_out, int out_size)
{
    const float* attn     = (const float*)d_in[0];
    const int*   in_lens  = (const int*)d_in[1];
    const int*   out_lens = (const int*)d_in[2];
    (void)in_sizes; (void)n_in; (void)out_size;

    cudaFuncSetAttribute(ctc_kernel,
                         cudaFuncAttributeMaxDynamicSharedMemorySize, RING_BYTES);
    ctc_kernel<<<BATCH, NTH, RING_BYTES>>>(attn, in_lens, out_lens, (float*)d_out);
}

// round 16
// speedup vs baseline: 2.3421x; 1.0477x over previous
#include <cuda_runtime.h>

#define TQ     900
#define TK     200
#define BATCH  128
#define LOG2E  1.4426950408889634f
#define LN2    0.6931471805599453f
#define EINV   0.36787944117144233f   // exp(-1): blank prob numerator
#define NTH    544                    // 16 producer warps + 1 DP warp (highest wid)
#define DPW    16
#define CR     16                     // rows per chunk
#define NSLOT  4                      // ring slots (64 rows total)
#define ROWF   256                    // floats per ring row (split-f4 layout)
#define RING_BYTES (NSLOT * CR * ROWF * 4)   // 64 KB dynamic smem

__device__ float g_losses[BATCH];
__device__ int   g_cnt = 0;

__device__ __forceinline__ float ex2f(float x) {
    float y; asm("ex2.approx.ftz.f32 %0, %1;" : "=f"(y) : "f"(x)); return y;
}
__device__ __forceinline__ float lg2f(float x) {
    float y; asm("lg2.approx.ftz.f32 %0, %1;" : "=f"(y) : "f"(x)); return y;
}
__device__ __forceinline__ float rcpf(float x) {
    float y; asm("rcp.approx.ftz.f32 %0, %1;" : "=f"(y) : "f"(x)); return y;
}
__device__ __forceinline__ unsigned redux_max_u32(unsigned v) {
    unsigned r; asm("redux.sync.max.u32 %0, %1, 0xffffffff;" : "=r"(r) : "r"(v));
    return r;
}
__device__ __forceinline__ void mbar_init(unsigned a, unsigned cnt) {
    asm volatile("mbarrier.init.shared.b64 [%0], %1;" :: "r"(a), "r"(cnt) : "memory");
}
__device__ __forceinline__ void mbar_arrive(unsigned a) {
    asm volatile("mbarrier.arrive.release.cta.shared::cta.b64 _, [%0];" :: "r"(a) : "memory");
}
__device__ __forceinline__ void mbar_wait(unsigned a, unsigned parity) {
    asm volatile(
        "{\n\t.reg .pred P;\n"
        "MW_%=:\n\t"
        "mbarrier.try_wait.parity.acquire.cta.shared::cta.b64 P, [%0], %1, 0x989680;\n\t"
        "@P bra.uni MWD_%=;\n\t"
        "bra.uni MW_%=;\n"
        "MWD_%=:\n\t}"
        :: "r"(a), "r"(parity) : "memory");
}

// One CTA per batch element. Warp 16 runs the CTC forward DP in linear
// (probability) domain with DEFERRED blank scaling: lane l owns pairs
// j=7l..7l+6; invariant ae_true[i] = ae~[i] * pb_prev. Per row:
//   tv_i  = fma(ae~[i], pb_prev, ao[i-1])   (7 FFMA)
//   ao[i] = (ao[i] + tv_i) * p_i            (7 FADD + 7 FMUL)
//   ae~[i] = tv_i                           (register rename, 0 ops)
// -> 21 fma-pipe ops/row (was 28): the single DP warp is issue-bound at
// rt=2/op, so this cuts its per-row floor ~25%. Rescale every 8 rows to
// ~2^90 via redux.sync (exponent accumulator C). Warps 0..15: 4 producer
// warps per ring slot (4 rows each), batch-loaded logits, pre-divided
// label-masked softmax probs in split-f4 layout; mbarrier full=128/empty=32.
__global__ __launch_bounds__(NTH, 1)
void ctc_kernel(const float* __restrict__ attn,
                const int*   __restrict__ in_lens,
                const int*   __restrict__ out_lens,
                float*       __restrict__ out)
{
    extern __shared__ __align__(16) float ring[];
    __shared__ __align__(8) unsigned long long s_full[NSLOT], s_empty[NSLOT];
    __shared__ float s_fe[224], s_fo[224];

    const int b    = blockIdx.x;
    const int tid  = threadIdx.x;
    const int lane = tid & 31;
    const int w    = tid >> 5;
    const int L       = in_lens[b];    // 100..200
    const int out_len = out_lens[b];   // 700..900
    const float* attn_b = attn + (size_t)b * TQ * TK;
    const int nchunks = (out_len + CR - 1) / CR;

    // init: unwritten prob slots must read 0 forever
    for (int i = tid; i < NSLOT * CR * ROWF; i += NTH) ring[i] = 0.f;
    if (tid < NSLOT) {
        mbar_init((unsigned)__cvta_generic_to_shared(&s_full[tid]), 128);
        mbar_init((unsigned)__cvta_generic_to_shared(&s_empty[tid]), 32);
    }
    __syncthreads();

    if (w < DPW) {
        // ------------- Producer warps (16): 4 per slot, 4 rows each -------
        const int slot = w >> 2;
        const int quar = w & 3;
        const unsigned fb = (unsigned)__cvta_generic_to_shared(&s_full[slot]);
        const unsigned eb = (unsigned)__cvta_generic_to_shared(&s_empty[slot]);

        int kk[7], widx[7]; bool kv[7];
        #pragma unroll
        for (int i = 0; i < 7; ++i) {
            kk[i] = lane + 32 * i;
            kv[i] = (kk[i] < TK);
            const int dpl = kk[i] / 7, q = kk[i] % 7;
            widx[i] = (q < 4) ? (dpl * 4 + q) : (128 + dpl * 4 + (q - 4));
        }
        const int pbidx = 128 + lane * 4 + 3;   // pad slot: pb for DP lane==lane

        unsigned pe = 1;                         // first empty-wait passes
        for (int c = slot; c < nchunks; c += NSLOT) {
            mbar_wait(eb, pe); pe ^= 1;
            const int base = c * CR + quar * 4;

            // batch-load 4 rows x 7 logits (28 LDG in flight)
            float x[4][7];
            #pragma unroll
            for (int r = 0; r < 4; ++r) {
                const int t = base + r;
                if (t < out_len) {
                    const float* row = attn_b + (size_t)t * TK;
                    #pragma unroll
                    for (int i = 0; i < 7; ++i)
                        x[r][i] = kv[i] ? __ldg(row + kk[i]) : 0.f;
                }
            }
            #pragma unroll
            for (int r = 0; r < 4; ++r) {
                const int t = base + r;
                if (t >= out_len) break;
                float e[7];
                float sum = 0.f;
                #pragma unroll
                for (int i = 0; i < 7; ++i) {
                    e[i] = kv[i] ? ex2f(x[r][i] * LOG2E) : 0.f;
                    sum += e[i];
                }
                #pragma unroll
                for (int off = 16; off; off >>= 1)
                    sum += __shfl_xor_sync(0xffffffffu, sum, off);
                sum += EINV;                     // blank term once, post-reduce
                float rd = rcpf(sum);
                rd = rd * (2.0f - sum * rd);     // NR: near-exact 1/sum
                float* rowp = ring + (size_t)(slot * CR + quar * 4 + r) * ROWF;
                #pragma unroll
                for (int i = 0; i < 7; ++i)
                    if (kv[i]) rowp[widx[i]] = (kk[i] < L) ? e[i] * rd : 0.f;
                rowp[pbidx] = EINV * rd;         // every lane writes its pad
            }
            mbar_arrive(fb);                     // release: orders the stores
        }
    } else {
        // ------------- DP warp (wid 16) -----------------------------------
        float ae[7], ao[7];                      // ae[] holds ae~ (deferred pb)
        #pragma unroll
        for (int i = 0; i < 7; ++i) { ae[i] = 0.f; ao[i] = 0.f; }
        float pbp = 1.f;                         // pb of previous row
        int C = 0;                               // stored = true * 2^C
        unsigned ph = 0;

        for (int c = 0; c < nchunks; ++c) {
            const int slot = c & (NSLOT - 1);
            mbar_wait((unsigned)__cvta_generic_to_shared(&s_full[slot]), ph);
            const float* rb = ring + (size_t)slot * CR * ROWF;

            // depth-2 rolling float4 loads (conflict-free LDS.128)
            float4 A0 = *(const float4*)(rb + lane * 4);
            float4 B0 = *(const float4*)(rb + 128 + lane * 4);
            float4 A1 = *(const float4*)(rb + ROWF + lane * 4);
            float4 B1 = *(const float4*)(rb + ROWF + 128 + lane * 4);

            const int nr = min(CR, out_len - c * CR);
            #pragma unroll
            for (int r = 0; r < CR; ++r) {
                if (r < nr) {
                    const float4 a  = A0;
                    const float4 bv = B0;
                    A0 = A1; B0 = B1;
                    if (r + 2 < CR) {
                        A1 = *(const float4*)(rb + (r + 2) * ROWF + lane * 4);
                        B1 = *(const float4*)(rb + (r + 2) * ROWF + 128 + lane * 4);
                    }
                    if (c == 0 && r == 0) {      // t = 0 init
                        if (lane == 0) { ae[0] = 1.0f; ao[0] = a.x; }
                        pbp = bv.w;              // ae_true = ae~ * pb_0
                        continue;
                    }
                    // shfl FIRST; its latency hides under pairs 1..6 math
                    float a1in = __shfl_up_sync(0xffffffffu, ao[6], 1);
                    float tv1 = fmaf(ae[1], pbp, ao[0]);
                    float tv2 = fmaf(ae[2], pbp, ao[1]);
                    float tv3 = fmaf(ae[3], pbp, ao[2]);
                    float tv4 = fmaf(ae[4], pbp, ao[3]);
                    float tv5 = fmaf(ae[5], pbp, ao[4]);
                    float tv6 = fmaf(ae[6], pbp, ao[5]);
                    ao[1] = (ao[1] + tv1) * a.y;   ae[1] = tv1;
                    ao[2] = (ao[2] + tv2) * a.z;   ae[2] = tv2;
                    ao[3] = (ao[3] + tv3) * a.w;   ae[3] = tv3;
                    ao[4] = (ao[4] + tv4) * bv.x;  ae[4] = tv4;
                    ao[5] = (ao[5] + tv5) * bv.y;  ae[5] = tv5;
                    ao[6] = (ao[6] + tv6) * bv.z;  ae[6] = tv6;
                    if (lane == 0) a1in = 0.f;
                    float tv0 = fmaf(ae[0], pbp, a1in);
                    ao[0] = (ao[0] + tv0) * a.x;   ae[0] = tv0;
                    pbp = bv.w;                  // advance pb carry
                }

                // rescale every 8 rows: renormalize max to ~2^90
                // (branchless; redux over positive-float bits)
                if ((r & 7) == 7) {
                    float m = 0.f;
                    #pragma unroll
                    for (int i = 0; i < 7; ++i) m = fmaxf(m, fmaxf(ae[i], ao[i]));
                    m = __uint_as_float(redux_max_u32(__float_as_uint(m)));
                    const int ebx = (__float_as_int(m) >> 23) & 255;
                    int sh = 217 - ebx;
                    sh = max(-120, min(120, sh));
                    const float sc = __int_as_float((sh + 127) << 23);
                    C += sh;
                    #pragma unroll
                    for (int i = 0; i < 7; ++i) { ae[i] *= sc; ao[i] *= sc; }
                }
            }
            mbar_arrive((unsigned)__cvta_generic_to_shared(&s_empty[slot]));
            if (slot == NSLOT - 1) ph ^= 1;
        }

        // fin = alpha at t=out_len-1; materialize true ae = ae~ * pb_last.
        // hi=fin[2L] (even of pair L), lo=fin[2L-1] (odd of pair L-1)
        #pragma unroll
        for (int i = 0; i < 7; ++i) {
            s_fe[lane * 7 + i] = ae[i] * pbp;
            s_fo[lane * 7 + i] = ao[i];
        }
        __syncwarp();
        if (lane == 0) {
            const float hi = s_fe[L];
            const float lo = s_fo[L - 1];
            float loss = -(lg2f(hi + lo) - (float)C) * LN2;
            if (!(loss < 1e20f)) loss = 0.0f;    // inf/NaN/huge -> 0 (ref rule)
            g_losses[b] = loss / (float)L;
            __threadfence();
            const int n = atomicAdd(&g_cnt, 1);
            if (n == BATCH - 1) {                // last CTA: deterministic mean
                __threadfence();
                float s = 0.f;
                for (int i = 0; i < BATCH; ++i) s += g_losses[i];
                out[0] = s * (1.0f / BATCH);
                g_cnt = 0;                       // reset for graph replay
                __threadfence();
            }
        }
    }
}

extern "C" void kernel_launch(void* const* d_in, const int* in_sizes, int n_in,
                              void* d_out, int out_size)
{
    const float* attn     = (const float*)d_in[0];
    const int*   in_lens  = (const int*)d_in[1];
    const int*   out_lens = (const int*)d_in[2];
    (void)in_sizes; (void)n_in; (void)out_size;

    cudaFuncSetAttribute(ctc_kernel,
                         cudaFuncAttributeMaxDynamicSharedMemorySize, RING_BYTES);
    ctc_kernel<<<BATCH, NTH, RING_BYTES>>>(attn, in_lens, out_lens, (float*)d_out);
}

// round 17
// speedup vs baseline: 4.5819x; 1.9563x over previous
#include <cuda_runtime.h>

#define TQ     900
#define TK     200
#define BATCH  128
#define LOG2E  1.4426950408889634f
#define LN2    0.6931471805599453f
#define EINV   0.36787944117144233f   // exp(-1): blank prob numerator
#define NTH    544                    // 16 producer warps + 1 DP warp (highest wid)
#define DPW    16
#define CR     16                     // rows per chunk
#define NSLOT  4                      // ring slots (64 rows total)
#define ROWF   256                    // floats per ring row (split-f4 layout)
#define RING_BYTES (NSLOT * CR * ROWF * 4)   // 64 KB dynamic smem

__device__ float g_losses[BATCH];
__device__ int   g_cnt = 0;

__device__ __forceinline__ float ex2f(float x) {
    float y; asm("ex2.approx.ftz.f32 %0, %1;" : "=f"(y) : "f"(x)); return y;
}
__device__ __forceinline__ float lg2f(float x) {
    float y; asm("lg2.approx.ftz.f32 %0, %1;" : "=f"(y) : "f"(x)); return y;
}
__device__ __forceinline__ float rcpf(float x) {
    float y; asm("rcp.approx.ftz.f32 %0, %1;" : "=f"(y) : "f"(x)); return y;
}
__device__ __forceinline__ unsigned redux_max_u32(unsigned v) {
    unsigned r; asm("redux.sync.max.u32 %0, %1, 0xffffffff;" : "=r"(r) : "r"(v));
    return r;
}
__device__ __forceinline__ void mbar_init(unsigned a, unsigned cnt) {
    asm volatile("mbarrier.init.shared.b64 [%0], %1;" :: "r"(a), "r"(cnt) : "memory");
}
__device__ __forceinline__ void mbar_arrive(unsigned a) {
    asm volatile("mbarrier.arrive.release.cta.shared::cta.b64 _, [%0];" :: "r"(a) : "memory");
}
__device__ __forceinline__ void mbar_wait(unsigned a, unsigned parity) {
    asm volatile(
        "{\n\t.reg .pred P;\n"
        "MW_%=:\n\t"
        "mbarrier.try_wait.parity.acquire.cta.shared::cta.b64 P, [%0], %1, 0x989680;\n\t"
        "@P bra.uni MWD_%=;\n\t"
        "bra.uni MW_%=;\n"
        "MWD_%=:\n\t}"
        :: "r"(a), "r"(parity) : "memory");
}

// DP row update (deferred blank scaling): ae[] holds ae~, true ae = ae~*pbp.
// 21 fma-pipe ops; shfl issued first so its 26-cyc latency hides under the
// independent pair-1..6 math. NO runtime branches.
#define DP_ROW(a_, bv_) do {                                            \
    float a1in = __shfl_up_sync(0xffffffffu, ao[6], 1);                 \
    float tv1 = fmaf(ae[1], pbp, ao[0]);                                \
    float tv2 = fmaf(ae[2], pbp, ao[1]);                                \
    float tv3 = fmaf(ae[3], pbp, ao[2]);                                \
    float tv4 = fmaf(ae[4], pbp, ao[3]);                                \
    float tv5 = fmaf(ae[5], pbp, ao[4]);                                \
    float tv6 = fmaf(ae[6], pbp, ao[5]);                                \
    ao[1] = (ao[1] + tv1) * (a_).y;   ae[1] = tv1;                      \
    ao[2] = (ao[2] + tv2) * (a_).z;   ae[2] = tv2;                      \
    ao[3] = (ao[3] + tv3) * (a_).w;   ae[3] = tv3;                      \
    ao[4] = (ao[4] + tv4) * (bv_).x;  ae[4] = tv4;                      \
    ao[5] = (ao[5] + tv5) * (bv_).y;  ae[5] = tv5;                      \
    ao[6] = (ao[6] + tv6) * (bv_).z;  ae[6] = tv6;                      \
    if (lane == 0) a1in = 0.f;                                          \
    float tv0 = fmaf(ae[0], pbp, a1in);                                 \
    ao[0] = (ao[0] + tv0) * (a_).x;   ae[0] = tv0;                      \
    pbp = (bv_).w;                                                      \
} while (0)

// branchless pow2 rescale: renormalize warp-max to ~2^90 (redux over
// positive-float bits); exact exponent bookkeeping in C.
#define DP_RESCALE() do {                                               \
    float m_ = 0.f;                                                     \
    _Pragma("unroll")                                                   \
    for (int i_ = 0; i_ < 7; ++i_) m_ = fmaxf(m_, fmaxf(ae[i_], ao[i_]));\
    m_ = __uint_as_float(redux_max_u32(__float_as_uint(m_)));           \
    const int eb_ = (__float_as_int(m_) >> 23) & 255;                   \
    int sh_ = 217 - eb_;                                                \
    sh_ = max(-120, min(120, sh_));                                     \
    const float sc_ = __int_as_float((sh_ + 127) << 23);                \
    C += sh_;                                                           \
    _Pragma("unroll")                                                   \
    for (int i_ = 0; i_ < 7; ++i_) { ae[i_] *= sc_; ao[i_] *= sc_; }    \
} while (0)

// One CTA per batch element. Warp 16 runs the CTC forward DP in linear
// (probability) domain, 7 state-pairs per lane in registers. The chunk loop
// is PEELED: chunk 0 (t=0 init) and the final partial chunk have their own
// paths; the steady-state loop processes guaranteed-full 16-row chunks with
// a fully-unrolled branch-free body (no BSSY/BSYNC envelopes per row).
// Warps 0..15: 4 producer warps per ring slot (4 rows each), batch-loaded
// logits, pre-divided label-masked softmax probs in split-f4 layout
// ([lane*4+i]=p0..3, [128+lane*4+i]=p4..6 + pb pad); mbar full=128/empty=32.
__global__ __launch_bounds__(NTH, 1)
void ctc_kernel(const float* __restrict__ attn,
                const int*   __restrict__ in_lens,
                const int*   __restrict__ out_lens,
                float*       __restrict__ out)
{
    extern __shared__ __align__(16) float ring[];
    __shared__ __align__(8) unsigned long long s_full[NSLOT], s_empty[NSLOT];
    __shared__ float s_fe[224], s_fo[224];

    const int b    = blockIdx.x;
    const int tid  = threadIdx.x;
    const int lane = tid & 31;
    const int w    = tid >> 5;
    const int L       = in_lens[b];    // 100..200
    const int out_len = out_lens[b];   // 700..900
    const float* attn_b = attn + (size_t)b * TQ * TK;
    const int nchunks = (out_len + CR - 1) / CR;   // >= 44

    // init: unwritten prob slots must read 0 forever
    for (int i = tid; i < NSLOT * CR * ROWF; i += NTH) ring[i] = 0.f;
    if (tid < NSLOT) {
        mbar_init((unsigned)__cvta_generic_to_shared(&s_full[tid]), 128);
        mbar_init((unsigned)__cvta_generic_to_shared(&s_empty[tid]), 32);
    }
    __syncthreads();

    if (w < DPW) {
        // ------------- Producer warps (16): 4 per slot, 4 rows each -------
        const int slot = w >> 2;
        const int quar = w & 3;
        const unsigned fb = (unsigned)__cvta_generic_to_shared(&s_full[slot]);
        const unsigned eb = (unsigned)__cvta_generic_to_shared(&s_empty[slot]);

        int kk[7], widx[7]; bool kv[7];
        #pragma unroll
        for (int i = 0; i < 7; ++i) {
            kk[i] = lane + 32 * i;
            kv[i] = (kk[i] < TK);
            const int dpl = kk[i] / 7, q = kk[i] % 7;
            widx[i] = (q < 4) ? (dpl * 4 + q) : (128 + dpl * 4 + (q - 4));
        }
        const int pbidx = 128 + lane * 4 + 3;   // pad slot: pb for DP lane==lane

        unsigned pe = 1;                         // first empty-wait passes
        for (int c = slot; c < nchunks; c += NSLOT) {
            mbar_wait(eb, pe); pe ^= 1;
            const int base = c * CR + quar * 4;

            // batch-load 4 rows x 7 logits (28 LDG in flight)
            float x[4][7];
            #pragma unroll
            for (int r = 0; r < 4; ++r) {
                const int t = base + r;
                if (t < out_len) {
                    const float* row = attn_b + (size_t)t * TK;
                    #pragma unroll
                    for (int i = 0; i < 7; ++i)
                        x[r][i] = kv[i] ? __ldg(row + kk[i]) : 0.f;
                }
            }
            #pragma unroll
            for (int r = 0; r < 4; ++r) {
                const int t = base + r;
                if (t >= out_len) break;
                float e[7];
                float sum = 0.f;
                #pragma unroll
                for (int i = 0; i < 7; ++i) {
                    e[i] = kv[i] ? ex2f(x[r][i] * LOG2E) : 0.f;
                    sum += e[i];
                }
                #pragma unroll
                for (int off = 16; off; off >>= 1)
                    sum += __shfl_xor_sync(0xffffffffu, sum, off);
                sum += EINV;                     // blank term once, post-reduce
                float rd = rcpf(sum);
                rd = rd * (2.0f - sum * rd);     // NR: near-exact 1/sum
                float* rowp = ring + (size_t)(slot * CR + quar * 4 + r) * ROWF;
                #pragma unroll
                for (int i = 0; i < 7; ++i)
                    if (kv[i]) rowp[widx[i]] = (kk[i] < L) ? e[i] * rd : 0.f;
                rowp[pbidx] = EINV * rd;         // every lane writes its pad
            }
            mbar_arrive(fb);                     // release: orders the stores
        }
    } else {
        // ------------- DP warp (wid 16) -----------------------------------
        float ae[7], ao[7];                      // ae[] holds ae~ (deferred pb)
        #pragma unroll
        for (int i = 0; i < 7; ++i) { ae[i] = 0.f; ao[i] = 0.f; }
        float pbp = 1.f;
        int C = 0;                               // stored = true * 2^C
        unsigned ph = 0;

        // ---- chunk 0 (full; contains t=0 init at r=0) --------------------
        {
            mbar_wait((unsigned)__cvta_generic_to_shared(&s_full[0]), ph);
            const float* rb = ring;
            float4 A0 = *(const float4*)(rb + lane * 4);
            float4 B0 = *(const float4*)(rb + 128 + lane * 4);
            float4 A1 = *(const float4*)(rb + ROWF + lane * 4);
            float4 B1 = *(const float4*)(rb + ROWF + 128 + lane * 4);

            // r = 0: init
            if (lane == 0) { ae[0] = 1.0f; ao[0] = A0.x; }
            pbp = B0.w;
            A0 = A1; B0 = B1;
            A1 = *(const float4*)(rb + 2 * ROWF + lane * 4);
            B1 = *(const float4*)(rb + 2 * ROWF + 128 + lane * 4);

            #pragma unroll
            for (int r = 1; r < CR; ++r) {
                const float4 a  = A0;
                const float4 bv = B0;
                A0 = A1; B0 = B1;
                if (r + 2 < CR) {
                    A1 = *(const float4*)(rb + (r + 2) * ROWF + lane * 4);
                    B1 = *(const float4*)(rb + (r + 2) * ROWF + 128 + lane * 4);
                }
                DP_ROW(a, bv);
                if ((r & 7) == 7) DP_RESCALE();
            }
            mbar_arrive((unsigned)__cvta_generic_to_shared(&s_empty[0]));
        }

        // ---- steady state: full chunks, branch-free row body -------------
        for (int c = 1; c < nchunks - 1; ++c) {
            const int slot = c & (NSLOT - 1);
            if (slot == 0) ph ^= 1;              // wrapped past slot 3
            mbar_wait((unsigned)__cvta_generic_to_shared(&s_full[slot]), ph);
            const float* rb = ring + (size_t)slot * CR * ROWF;

            float4 A0 = *(const float4*)(rb + lane * 4);
            float4 B0 = *(const float4*)(rb + 128 + lane * 4);
            float4 A1 = *(const float4*)(rb + ROWF + lane * 4);
            float4 B1 = *(const float4*)(rb + ROWF + 128 + lane * 4);

            #pragma unroll
            for (int r = 0; r < CR; ++r) {
                const float4 a  = A0;
                const float4 bv = B0;
                A0 = A1; B0 = B1;
                if (r + 2 < CR) {
                    A1 = *(const float4*)(rb + (r + 2) * ROWF + lane * 4);
                    B1 = *(const float4*)(rb + (r + 2) * ROWF + 128 + lane * 4);
                }
                DP_ROW(a, bv);
                if ((r & 7) == 7) DP_RESCALE();
            }
            mbar_arrive((unsigned)__cvta_generic_to_shared(&s_empty[slot]));
        }

        // ---- last chunk (possibly partial; guarded path) -----------------
        {
            const int c    = nchunks - 1;
            const int slot = c & (NSLOT - 1);
            if (slot == 0) ph ^= 1;
            mbar_wait((unsigned)__cvta_generic_to_shared(&s_full[slot]), ph);
            const float* rb = ring + (size_t)slot * CR * ROWF;
            const int nr = out_len - c * CR;     // 1..16

            float4 A0 = *(const float4*)(rb + lane * 4);
            float4 B0 = *(const float4*)(rb + 128 + lane * 4);
            float4 A1 = *(const float4*)(rb + ROWF + lane * 4);
            float4 B1 = *(const float4*)(rb + ROWF + 128 + lane * 4);

            #pragma unroll
            for (int r = 0; r < CR; ++r) {
                if (r < nr) {
                    const float4 a  = A0;
                    const float4 bv = B0;
                    A0 = A1; B0 = B1;
                    if (r + 2 < CR) {
                        A1 = *(const float4*)(rb + (r + 2) * ROWF + lane * 4);
                        B1 = *(const float4*)(rb + (r + 2) * ROWF + 128 + lane * 4);
                    }
                    DP_ROW(a, bv);
                }
                if ((r & 7) == 7) DP_RESCALE();
            }
            mbar_arrive((unsigned)__cvta_generic_to_shared(&s_empty[slot]));
        }

        // fin = alpha at t=out_len-1; materialize true ae = ae~ * pb_last.
        // hi=fin[2L] (even of pair L), lo=fin[2L-1] (odd of pair L-1)
        #pragma unroll
        for (int i = 0; i < 7; ++i) {
            s_fe[lane * 7 + i] = ae[i] * pbp;
            s_fo[lane * 7 + i] = ao[i];
        }
        __syncwarp();
        if (lane == 0) {
            const float hi = s_fe[L];
            const float lo = s_fo[L - 1];
            float loss = -(lg2f(hi + lo) - (float)C) * LN2;
            if (!(loss < 1e20f)) loss = 0.0f;    // inf/NaN/huge -> 0 (ref rule)
            g_losses[b] = loss / (float)L;
            __threadfence();
            const int n = atomicAdd(&g_cnt, 1);
            if (n == BATCH - 1) {                // last CTA: deterministic mean
                __threadfence();
                float s = 0.f;
                for (int i = 0; i < BATCH; ++i) s += g_losses[i];
                out[0] = s * (1.0f / BATCH);
                g_cnt = 0;                       // reset for graph replay
                __threadfence();
            }
        }
    }
}

extern "C" void kernel_launch(void* const* d_in, const int* in_sizes, int n_in,
                              void* d_out, int out_size)
{
    const float* attn     = (const float*)d_in[0];
    const int*   in_lens  = (const int*)d_in[1];
    const int*   out_lens = (const int*)d_in[2];
    (void)in_sizes; (void)n_in; (void)out_size;

    cudaFuncSetAttribute(ctc_kernel,
                         cudaFuncAttributeMaxDynamicSharedMemorySize, RING_BYTES);
    ctc_kernel<<<BATCH, NTH, RING_BYTES>>>(attn, in_lens, out_lens, (float*)d_out);
}